// round 1
// baseline (speedup 1.0000x reference)
#include <cuda_runtime.h>
#include <cstdint>

#define MCN    50000
#define TSTEPS 180
#define NOPT   32
#define BDIM   352
#define NWARP  11
#define PPB    338
#define NBLK   148

#define HSTEP  (1.0f/360.0f)
#define RATEC  0.025f

// ---------- packed f32x2 helpers ----------
struct F2 { unsigned long long v; };

__device__ __forceinline__ F2 f2pack(float lo, float hi) {
    F2 r; asm("mov.b64 %0, {%1,%2};" : "=l"(r.v) : "f"(lo), "f"(hi)); return r;
}
__device__ __forceinline__ void f2unpack(F2 a, float& lo, float& hi) {
    asm("mov.b64 {%0,%1}, %2;" : "=f"(lo), "=f"(hi) : "l"(a.v));
}
__device__ __forceinline__ F2 f2of(unsigned long long u) { F2 r; r.v = u; return r; }
__device__ __forceinline__ F2 f2fma(F2 a, F2 b, F2 c) {
    F2 d; asm("fma.rn.f32x2 %0, %1, %2, %3;" : "=l"(d.v) : "l"(a.v), "l"(b.v), "l"(c.v));
    return d;
}
__device__ __forceinline__ F2 f2relu(F2 a) {
    float lo, hi; f2unpack(a, lo, hi);
    return f2pack(fmaxf(lo, 0.0f), fmaxf(hi, 0.0f));
}
__device__ __forceinline__ F2 f2dup(float w) { return f2pack(w, w); }

// ---------- global scratch (block partial sums) ----------
__device__ float g_part[NBLK * NOPT];

// ---------- shared memory layout (bytes) ----------
#define OFF_W2D   0         // 4*64*64 F2 = 131072
#define OFF_W1S   131072    // 256 F2 = 2048
#define OFF_W1V   133120
#define OFF_C1    135168
#define OFF_B2    137216
#define OFF_WO    139264
#define OFF_BO    141312    // 4 F2 = 32
#define OFF_W1R   141344    // 1024 f = 4096
#define OFF_B1R   145440    // 256 f = 1024
#define OFF_STRK  146464    // 32 f = 128
#define OFF_MASK  146592    // 180 u32 = 720
#define OFF_WPART 147312    // 352 f = 1408
#define SMEM_BYTES 148720

__global__ __launch_bounds__(BDIM, 1)
void sde_mc_kernel(const float* __restrict__ x,
                   const float* __restrict__ z,
                   const float* __restrict__ z1,
                   const float* __restrict__ W1,
                   const float* __restrict__ b1,
                   const float* __restrict__ W2,
                   const float* __restrict__ b2,
                   const float* __restrict__ Wo,
                   const float* __restrict__ bo)
{
    extern __shared__ char sm[];
    F2*       W2d   = (F2*)(sm + OFF_W2D);
    F2*       w1S2  = (F2*)(sm + OFF_W1S);
    F2*       w1V2  = (F2*)(sm + OFF_W1V);
    F2*       c12   = (F2*)(sm + OFF_C1);
    F2*       b22   = (F2*)(sm + OFF_B2);
    F2*       Wo2   = (F2*)(sm + OFF_WO);
    F2*       bo2   = (F2*)(sm + OFF_BO);
    float*    W1r   = (float*)(sm + OFF_W1R);
    float*    b1r   = (float*)(sm + OFF_B1R);
    float*    strk  = (float*)(sm + OFF_STRK);
    unsigned* maskS = (unsigned*)(sm + OFF_MASK);
    float*    wpart = (float*)(sm + OFF_WPART);

    const int tid = threadIdx.x;

    // ---- init shared state ----
    for (int i = tid; i < 4 * 64 * 64; i += BDIM) W2d[i] = f2dup(W2[i]);
    for (int i = tid; i < 256; i += BDIM) {
        w1S2[i] = f2dup(W1[4 * i + 1]);
        w1V2[i] = f2dup(W1[4 * i + 2]);
        b22[i]  = f2dup(b2[i]);
        Wo2[i]  = f2dup(Wo[i]);
        b1r[i]  = b1[i];
    }
    for (int i = tid; i < 1024; i += BDIM) W1r[i] = W1[i];
    if (tid < 4)    bo2[tid]  = f2dup(bo[tid]);
    if (tid < NOPT) strk[tid] = x[2 * tid + 1];
    if (tid < TSTEPS) {
        unsigned m = 0;
        for (int k = 0; k < NOPT; k++)
            if ((int)x[2 * k] == tid + 1) m |= (1u << k);
        maskS[tid] = m;
    }
    for (int i = tid; i < NOPT * NWARP; i += BDIM) wpart[i] = 0.0f;
    __syncthreads();

    // ---- path setup (antithetic pair packed in f32x2) ----
    const int  pair  = blockIdx.x * PPB + tid;
    const bool valid = (tid < PPB) && (pair < MCN);
    const int  pl    = valid ? pair : 0;
    const float* zr  = z  + (long)pl * TSTEPS;
    const float* z1r = z1 + (long)pl * TSTEPS;

    const float SQH  = sqrtf(HSTEP);
    const float SQ75 = 0.8660254037844386f;
    const F2 H2 = f2dup(HSTEP);

    F2 S = f2pack(100.0f, 100.0f);
    F2 V = f2pack(0.04f, 0.04f);

    const int lane = tid & 31;
    const int wid  = tid >> 5;

    for (int i = 0; i < TSTEPS; i++) {
        __syncthreads();  // previous-step consumers of c12 are done
        if (tid < 256) {
            float t = (float)i * HSTEP;
            float c = fmaf(W1r[4 * tid + 0], t,
                      fmaf(W1r[4 * tid + 3], RATEC, b1r[tid]));
            c12[tid] = f2dup(c);
        }
        __syncthreads();

        float za  = __ldg(zr + i);
        float zba = __ldg(z1r + i);
        float z1c = fmaf(SQ75, zba, -0.5f * za);
        float dwa  = SQH * za;
        float dw1a = SQH * z1c;
        F2 dW  = f2pack(dwa,  -dwa);
        F2 dW1 = f2pack(dw1a, -dw1a);

        F2 SA = S, VA = V;

        #pragma unroll 1
        for (int n = 0; n < 4; n++) {
            // ---- layer 1: h1 = relu(w1S*S + w1V*V + c1) ----
            F2 h1[64];
            const ulonglong2* pS = (const ulonglong2*)(w1S2 + n * 64);
            const ulonglong2* pV = (const ulonglong2*)(w1V2 + n * 64);
            const ulonglong2* pC = (const ulonglong2*)(c12  + n * 64);
            #pragma unroll
            for (int j = 0; j < 32; j++) {
                ulonglong2 ws = pS[j], wv = pV[j], cc = pC[j];
                F2 t0 = f2fma(f2of(ws.x), S, f2of(cc.x));
                t0 = f2fma(f2of(wv.x), V, t0);
                h1[2 * j] = f2relu(t0);
                F2 t1 = f2fma(f2of(ws.y), S, f2of(cc.y));
                t1 = f2fma(f2of(wv.y), V, t1);
                h1[2 * j + 1] = f2relu(t1);
            }
            // ---- layer 2 + output layer fused ----
            F2 oacc = bo2[n];
            const ulonglong2* wbase = (const ulonglong2*)(W2d + n * 64 * 64);
            const F2* b2n = b22 + n * 64;
            const F2* won = Wo2 + n * 64;
            #pragma unroll 1
            for (int v = 0; v < 64; v += 2) {
                F2 a0 = b2n[v], a1 = b2n[v + 1];
                const ulonglong2* r0 = wbase + v * 32;
                const ulonglong2* r1 = r0 + 32;
                #pragma unroll
                for (int q = 0; q < 32; q++) {
                    ulonglong2 w0 = r0[q], w1 = r1[q];
                    a0 = f2fma(f2of(w0.x), h1[2 * q],     a0);
                    a0 = f2fma(f2of(w0.y), h1[2 * q + 1], a0);
                    a1 = f2fma(f2of(w1.x), h1[2 * q],     a1);
                    a1 = f2fma(f2of(w1.y), h1[2 * q + 1], a1);
                }
                oacc = f2fma(won[v],     f2relu(a0), oacc);
                oacc = f2fma(won[v + 1], f2relu(a1), oacc);
            }
            // apply: n0 -> S drift, n1 -> S diffusion, n2 -> V drift, n3 -> V diffusion
            if (n == 0) SA = f2fma(oacc, H2,  SA);
            if (n == 1) SA = f2fma(oacc, dW,  SA);
            if (n == 2) VA = f2fma(oacc, H2,  VA);
            if (n == 3) VA = f2fma(oacc, dW1, VA);
        }

        S = f2relu(SA);   // max(., 0) clamp
        V = f2relu(VA);

        // ---- payoff events for options maturing at path index i+1 ----
        unsigned m = maskS[i];
        while (m) {
            int k = __ffs(m) - 1; m &= m - 1;
            float Kk = strk[k];
            float slo, shi; f2unpack(S, slo, shi);
            float p = valid ? (fmaxf(slo - Kk, 0.0f) + fmaxf(shi - Kk, 0.0f)) : 0.0f;
            #pragma unroll
            for (int off = 16; off; off >>= 1)
                p += __shfl_down_sync(0xffffffffu, p, off);
            if (lane == 0) wpart[k * NWARP + wid] = p;
        }
    }

    __syncthreads();
    if (tid < NOPT) {
        float s = 0.0f;
        #pragma unroll 1
        for (int w = 0; w < NWARP; w++) s += wpart[tid * NWARP + w];
        g_part[blockIdx.x * NOPT + tid] = s;
    }
}

__global__ void finalize_kernel(const float* __restrict__ x, float* __restrict__ out)
{
    int k = threadIdx.x;
    if (k < NOPT) {
        float s = 0.0f;
        #pragma unroll 1
        for (int b = 0; b < NBLK; b++) s += g_part[b * NOPT + k];
        float mat = x[2 * k];
        out[k] = (s / (2.0f * (float)MCN)) * expf(-RATEC * mat / 360.0f);
    }
}

extern "C" void kernel_launch(void* const* d_in, const int* in_sizes, int n_in,
                              void* d_out, int out_size)
{
    (void)in_sizes; (void)n_in; (void)out_size;
    const float* x  = (const float*)d_in[0];
    const float* z  = (const float*)d_in[1];
    const float* z1 = (const float*)d_in[2];
    const float* W1 = (const float*)d_in[3];
    const float* b1 = (const float*)d_in[4];
    const float* W2 = (const float*)d_in[5];
    const float* b2 = (const float*)d_in[6];
    const float* Wo = (const float*)d_in[7];
    const float* bo = (const float*)d_in[8];

    cudaFuncSetAttribute(sde_mc_kernel,
                         cudaFuncAttributeMaxDynamicSharedMemorySize, SMEM_BYTES);
    sde_mc_kernel<<<NBLK, BDIM, SMEM_BYTES>>>(x, z, z1, W1, b1, W2, b2, Wo, bo);
    finalize_kernel<<<1, 32>>>(x, (float*)d_out);
}